// round 3
// baseline (speedup 1.0000x reference)
#include <cuda_runtime.h>

#define NB  4
#define NPT 16384
#define NQ  1024
#define KK  20
#define KK1 21

// output layout (all f32, concatenated in reference return order)
#define OFF_IND 0
#define OFF_Q   (NB*NQ)                   // 4096
#define OFF_NM  (OFF_Q  + NB*NQ*3)        // 16384
#define OFF_DM  (OFF_NM + NB*NQ*KK)       // 98304
#define OFF_NO  (OFF_DM + NB*NQ*KK*3)     // 344064
#define OFF_DO  (OFF_NO + NB*NQ*KK)       // 425984

__device__ float g_query[NB*NQ*3];   // sampled query coords scratch

// ---------------------------------------------------------------------------
// FPS: one CTA per batch. Points in SMEM (SoA). Per-thread 16 min-dists in
// registers. Block argmax with first-index tie-break via packed u64 key.
// Distance form matches reference scan: sum((p - q)^2) with plain mul/add.
// ---------------------------------------------------------------------------
__global__ __launch_bounds__(1024, 1)
void fps_kernel(const float* __restrict__ pts, float* __restrict__ out)
{
    extern __shared__ float sm[];
    float* sx = sm;
    float* sy = sm + NPT;
    float* sz = sm + 2 * NPT;
    __shared__ unsigned long long s_part[32];
    __shared__ float s_q[3];

    const int b   = blockIdx.x;
    const int tid = threadIdx.x;
    const float* P = pts + (size_t)b * NPT * 3;

    // coalesced load, scatter into SoA
    for (int f = tid; f < NPT * 3; f += 1024) {
        float v = P[f];
        int i = f / 3, c = f - i * 3;
        if (c == 0)      sx[i] = v;
        else if (c == 1) sy[i] = v;
        else             sz[i] = v;
    }
    if (tid == 0) {
        float ax = P[0], ay = P[1], az = P[2];
        s_q[0] = ax; s_q[1] = ay; s_q[2] = az;
        out[OFF_IND + b * NQ] = 0.0f;
        float* oq = out + OFF_Q + (size_t)b * NQ * 3;
        oq[0] = ax; oq[1] = ay; oq[2] = az;
        float* gq = g_query + b * NQ * 3;
        gq[0] = ax; gq[1] = ay; gq[2] = az;
    }
    __syncthreads();

    float mind[16];
#pragma unroll
    for (int j = 0; j < 16; ++j) mind[j] = 1e10f;

    float qx = s_q[0], qy = s_q[1], qz = s_q[2];
    const int lane = tid & 31, wid = tid >> 5;

    for (int it = 1; it < NQ; ++it) {
        float bv = -1.0f;
        int   bi = 0;
#pragma unroll
        for (int j = 0; j < 16; ++j) {
            int i = j * 1024 + tid;
            float t0 = sx[i] - qx;
            float t1 = sy[i] - qy;
            float t2 = sz[i] - qz;
            // plain (non-contracted) sum of squares, left-to-right
            float d = __fadd_rn(__fadd_rn(__fmul_rn(t0, t0), __fmul_rn(t1, t1)),
                                __fmul_rn(t2, t2));
            float m = fminf(mind[j], d);
            mind[j] = m;
            if (m > bv) { bv = m; bi = i; }   // strict > keeps smallest index
        }
        unsigned long long key =
            ((unsigned long long)__float_as_uint(bv) << 32) |
            (unsigned)(0xFFFFFFFFu - (unsigned)bi);
#pragma unroll
        for (int o = 16; o; o >>= 1) {
            unsigned long long ok = __shfl_xor_sync(0xffffffffu, key, o);
            if (ok > key) key = ok;
        }
        if (lane == 0) s_part[wid] = key;
        __syncthreads();
        if (tid < 32) {
            unsigned long long k2 = s_part[tid];
#pragma unroll
            for (int o = 16; o; o >>= 1) {
                unsigned long long ok = __shfl_xor_sync(0xffffffffu, k2, o);
                if (ok > k2) k2 = ok;
            }
            if (tid == 0) {
                unsigned g = 0xFFFFFFFFu - (unsigned)(k2 & 0xFFFFFFFFu);
                float ax = sx[g], ay = sy[g], az = sz[g];
                s_q[0] = ax; s_q[1] = ay; s_q[2] = az;
                out[OFF_IND + b * NQ + it] = (float)g;
                float* oq = out + OFF_Q + ((size_t)b * NQ + it) * 3;
                oq[0] = ax; oq[1] = ay; oq[2] = az;
                float* gq = g_query + (b * NQ + it) * 3;
                gq[0] = ax; gq[1] = ay; gq[2] = az;
            }
        }
        __syncthreads();
        qx = s_q[0]; qy = s_q[1]; qz = s_q[2];
    }
}

// ---------------------------------------------------------------------------
// KNN: warp-per-query exact top-(K+1) selection, ascending distance with
// lower-index tie-break (key = dist_bits<<32 | idx). Candidate-buffer filter
// with running 21st-best threshold; periodic warp merge.
// Distance matches reference pdist2: (sq_q + sq_p) - 2*dot (dot = FMA chain),
// clamped to >= 0.
// ---------------------------------------------------------------------------
__device__ __forceinline__ unsigned long long u64min(unsigned long long a,
                                                     unsigned long long b)
{ return a < b ? a : b; }

__device__ __forceinline__ void knn_flush(unsigned long long& cand,
                                          unsigned long long& curT,
                                          int& cnt,
                                          unsigned long long* buf,
                                          int lane)
{
    __syncwarp(0xffffffffu);
    unsigned long long r0 = cand;
    unsigned long long r1 = (lane      < cnt) ? buf[lane]      : ~0ULL;
    unsigned long long r2 = (lane + 32 < cnt) ? buf[lane + 32] : ~0ULL;
    unsigned long long r3 = (lane + 64 < cnt) ? buf[lane + 64] : ~0ULL;
    unsigned long long nc = ~0ULL;
#pragma unroll
    for (int r = 0; r < KK1; ++r) {
        unsigned long long m = u64min(u64min(r0, r1), u64min(r2, r3));
#pragma unroll
        for (int o = 16; o; o >>= 1) {
            unsigned long long om = __shfl_xor_sync(0xffffffffu, m, o);
            if (om < m) m = om;
        }
        if (lane == r) nc = m;
        if (r0 == m) r0 = ~0ULL;
        else if (r1 == m) r1 = ~0ULL;
        else if (r2 == m) r2 = ~0ULL;
        else if (r3 == m) r3 = ~0ULL;
    }
    cand = nc;
    curT = __shfl_sync(0xffffffffu, nc, KK1 - 1);
    cnt  = 0;
    __syncwarp(0xffffffffu);
}

// mode 0: candidates = full point cloud (npts = NPT), mode 1: candidates =
// sampled queries themselves (npts = NQ, read from g_query).
__global__ __launch_bounds__(256)
void knn_kernel(const float* __restrict__ pts, int npts, int mode,
                float* __restrict__ outNbr, float* __restrict__ outD)
{
    __shared__ unsigned long long s_buf[8][96];
    const int warp = threadIdx.x >> 5;
    const int lane = threadIdx.x & 31;
    const int wg   = blockIdx.x * 8 + warp;      // 0..4095
    const int b    = wg >> 10;
    const int m    = wg & 1023;

    const float* Q = g_query + (b * NQ + m) * 3;
    float qx = Q[0], qy = Q[1], qz = Q[2];
    float sqq = __fadd_rn(__fadd_rn(__fmul_rn(qx, qx), __fmul_rn(qy, qy)),
                          __fmul_rn(qz, qz));

    const float* Pb = (mode == 0) ? (pts + (size_t)b * NPT * 3)
                                  : (g_query + b * NQ * 3);

    unsigned long long cand = ~0ULL, curT = ~0ULL;
    int cnt = 0;
    unsigned long long* buf = s_buf[warp];

    const int steps = npts >> 5;
    for (int j = 0; j < steps; ++j) {
        int i = (j << 5) + lane;
        const float* pp = Pb + i * 3;
        float px = __ldg(pp), py = __ldg(pp + 1), pz = __ldg(pp + 2);
        float sqp = __fadd_rn(__fadd_rn(__fmul_rn(px, px), __fmul_rn(py, py)),
                              __fmul_rn(pz, pz));
        float dot = __fmaf_rn(qz, pz, __fmaf_rn(qy, py, __fmul_rn(qx, px)));
        float d = fmaxf(__fsub_rn(__fadd_rn(sqq, sqp), __fmul_rn(2.0f, dot)),
                        0.0f);
        unsigned long long key =
            ((unsigned long long)__float_as_uint(d) << 32) | (unsigned)i;
        bool ins = key < curT;
        unsigned bal = __ballot_sync(0xffffffffu, ins);
        if (ins) buf[cnt + __popc(bal & ((1u << lane) - 1u))] = key;
        cnt += __popc(bal);
        if (cnt >= 64) knn_flush(cand, curT, cnt, buf, lane);
    }
    if (cnt > 0) knn_flush(cand, curT, cnt, buf, lane);

    // cand across lanes 0..20 holds the 21 nearest in ascending order.
    // Drop lane 0 (self / closest), emit lanes 1..20.
    if (lane >= 1 && lane < KK1) {
        unsigned idx = (unsigned)(cand & 0xFFFFFFFFu);
        size_t o = (size_t)wg * KK + (lane - 1);
        outNbr[o] = (float)idx;
        const float* ps = Pb + idx * 3;
        outD[o * 3 + 0] = qx - ps[0];
        outD[o * 3 + 1] = qy - ps[1];
        outD[o * 3 + 2] = qz - ps[2];
    }
}

extern "C" void kernel_launch(void* const* d_in, const int* in_sizes, int n_in,
                              void* d_out, int out_size)
{
    const float* points = (const float*)d_in[0];
    float* out = (float*)d_out;

    cudaFuncSetAttribute(fps_kernel,
                         cudaFuncAttributeMaxDynamicSharedMemorySize,
                         NPT * 3 * sizeof(float));

    fps_kernel<<<NB, 1024, NPT * 3 * sizeof(float)>>>(points, out);

    // Gmid: neighbors of queries among all N points
    knn_kernel<<<(NB * NQ) / 8, 256>>>(points, NPT, 0,
                                       out + OFF_NM, out + OFF_DM);
    // Gout: neighbors of queries among queries
    knn_kernel<<<(NB * NQ) / 8, 256>>>(points, NQ, 1,
                                       out + OFF_NO, out + OFF_DO);
}

// round 4
// speedup vs baseline: 1.4116x; 1.4116x over previous
#include <cuda_runtime.h>

#define NB  4
#define NPT 16384
#define NQ  1024
#define KK  20
#define KK1 21
#define NCELL 4096

// output layout (all f32, concatenated in reference return order)
#define OFF_IND 0
#define OFF_Q   (NB*NQ)                   // 4096
#define OFF_NM  (OFF_Q  + NB*NQ*3)        // 16384
#define OFF_DM  (OFF_NM + NB*NQ*KK)       // 98304
#define OFF_NO  (OFF_DM + NB*NQ*KK*3)     // 344064
#define OFF_DO  (OFF_NO + NB*NQ*KK)       // 425984

__device__ float    g_query[NB*NQ*3];   // sampled query coords scratch
__device__ unsigned g_sidx[NB*NPT];     // sorted-pos -> original index

__device__ __forceinline__ unsigned morton4(unsigned cx, unsigned cy, unsigned cz)
{
    unsigned m = 0;
#pragma unroll
    for (int b = 0; b < 4; ++b)
        m |= (((cx >> b) & 1u) << (3 * b))
           | (((cy >> b) & 1u) << (3 * b + 1))
           | (((cz >> b) & 1u) << (3 * b + 2));
    return m;
}

__device__ __forceinline__ unsigned cellof(float x, float y, float z)
{
    unsigned cx = (unsigned)fminf(fmaxf((x + 4.0f) * 2.0f, 0.0f), 15.0f);
    unsigned cy = (unsigned)fminf(fmaxf((y + 4.0f) * 2.0f, 0.0f), 15.0f);
    unsigned cz = (unsigned)fminf(fmaxf((z + 4.0f) * 2.0f, 0.0f), 15.0f);
    return morton4(cx, cy, cz);
}

// ---------------------------------------------------------------------------
// Bucketed FPS: one CTA per batch. Points Morton-counting-sorted into SMEM
// (SoA, transposed so thread t's 16 bucket points sit at [j*1024 + t] —
// conflict-free). Each thread owns one bucket: 16 packed u64 keys
// (min_d_bits<<32 | ~orig_idx) in registers + bbox. Per iteration a bucket
// updates only if its bbox lower-bound distance to q can beat its max min_d
// (skips are provably exact no-ops). Block argmax over bucket keys keeps the
// reference's first-index tie-break. Distance form matches the reference
// scan exactly: plain (non-contracted) sum of squares.
// ---------------------------------------------------------------------------
__global__ __launch_bounds__(1024, 1)
void fps_kernel(const float* __restrict__ pts, float* __restrict__ out)
{
    extern __shared__ float sm[];
    float*    sx   = sm;
    float*    sy   = sm + NPT;
    float*    sz   = sm + 2 * NPT;
    unsigned* hist = (unsigned*)(sm + 3 * NPT);

    __shared__ unsigned long long s_part[32];
    __shared__ unsigned long long s_win;
    __shared__ float s_q[3];
    __shared__ unsigned s_wsum[32];

    const int b    = blockIdx.x;
    const int tid  = threadIdx.x;
    const int lane = tid & 31, wid = tid >> 5;
    const float* P = pts + (size_t)b * NPT * 3;
    unsigned* sidx = g_sidx + b * NPT;

    // ---- counting sort by Morton cell ----
#pragma unroll
    for (int k = 0; k < 4; ++k) hist[tid + k * 1024] = 0;
    __syncthreads();

#pragma unroll
    for (int k = 0; k < 16; ++k) {
        int i = tid + k * 1024;
        float x = P[i * 3], y = P[i * 3 + 1], z = P[i * 3 + 2];
        atomicAdd(&hist[cellof(x, y, z)], 1u);
    }
    __syncthreads();

    // exclusive scan of hist[4096] in place
    unsigned v0 = hist[4 * tid], v1 = hist[4 * tid + 1];
    unsigned v2 = hist[4 * tid + 2], v3 = hist[4 * tid + 3];
    unsigned s = v0 + v1 + v2 + v3;
    unsigned inc = s;
#pragma unroll
    for (int o = 1; o < 32; o <<= 1) {
        unsigned n = __shfl_up_sync(0xffffffffu, inc, o);
        if (lane >= o) inc += n;
    }
    if (lane == 31) s_wsum[wid] = inc;
    __syncthreads();
    if (tid < 32) {
        unsigned w = s_wsum[tid], wi = w;
#pragma unroll
        for (int o = 1; o < 32; o <<= 1) {
            unsigned n = __shfl_up_sync(0xffffffffu, wi, o);
            if (tid >= o) wi += n;
        }
        s_wsum[tid] = wi - w;   // exclusive warp base
    }
    __syncthreads();
    unsigned base = s_wsum[wid] + inc - s;
    hist[4 * tid]     = base;
    hist[4 * tid + 1] = base + v0;
    hist[4 * tid + 2] = base + v0 + v1;
    hist[4 * tid + 3] = base + v0 + v1 + v2;
    __syncthreads();

    // scatter into transposed SoA: sorted pos p -> smem slot (p%16)*1024 + p/16
#pragma unroll
    for (int k = 0; k < 16; ++k) {
        int i = tid + k * 1024;
        float x = P[i * 3], y = P[i * 3 + 1], z = P[i * 3 + 2];
        unsigned pos = atomicAdd(&hist[cellof(x, y, z)], 1u);
        int slot = (int)(pos & 15u) * 1024 + (int)(pos >> 4);
        sx[slot] = x; sy[slot] = y; sz[slot] = z;
        sidx[pos] = (unsigned)i;
    }
    __syncthreads();

    // ---- per-bucket state: keys + bbox ----
    unsigned long long key[16];
    float lox = 1e30f, loy = 1e30f, loz = 1e30f;
    float hix = -1e30f, hiy = -1e30f, hiz = -1e30f;
    const unsigned long long HI10 =
        ((unsigned long long)__float_as_uint(1e10f)) << 32;
    unsigned long long bkey = 0;
#pragma unroll
    for (int j = 0; j < 16; ++j) {
        float x = sx[j * 1024 + tid];
        float y = sy[j * 1024 + tid];
        float z = sz[j * 1024 + tid];
        lox = fminf(lox, x); hix = fmaxf(hix, x);
        loy = fminf(loy, y); hiy = fmaxf(hiy, y);
        loz = fminf(loz, z); hiz = fmaxf(hiz, z);
        key[j] = HI10 | (unsigned)(~sidx[16 * tid + j]);
        bkey = bkey > key[j] ? bkey : key[j];
    }

    if (tid == 0) {
        float ax = P[0], ay = P[1], az = P[2];
        s_q[0] = ax; s_q[1] = ay; s_q[2] = az;
        out[OFF_IND + b * NQ] = 0.0f;
        float* oq = out + OFF_Q + (size_t)b * NQ * 3;
        oq[0] = ax; oq[1] = ay; oq[2] = az;
        float* gq = g_query + b * NQ * 3;
        gq[0] = ax; gq[1] = ay; gq[2] = az;
    }
    __syncthreads();
    float qx = s_q[0], qy = s_q[1], qz = s_q[2];

    // ---- main FPS loop ----
    for (int it = 1; it < NQ; ++it) {
        // bbox lower bound to q; skip bucket if provably no-op
        float dx = fmaxf(fmaxf(lox - qx, qx - hix), 0.0f);
        float dy = fmaxf(fmaxf(loy - qy, qy - hiy), 0.0f);
        float dz = fmaxf(fmaxf(loz - qz, qz - hiz), 0.0f);
        float lb2 = dx * dx + dy * dy + dz * dz;
        float bm = __uint_as_float((unsigned)(bkey >> 32));
        if (lb2 * 0.999f < bm) {
            unsigned long long nb = 0;
#pragma unroll
            for (int j = 0; j < 16; ++j) {
                float t0 = sx[j * 1024 + tid] - qx;
                float t1 = sy[j * 1024 + tid] - qy;
                float t2 = sz[j * 1024 + tid] - qz;
                // plain (non-contracted) sum of squares, left-to-right
                float d = __fadd_rn(__fadd_rn(__fmul_rn(t0, t0),
                                              __fmul_rn(t1, t1)),
                                    __fmul_rn(t2, t2));
                unsigned db = __float_as_uint(d);
                if (db < (unsigned)(key[j] >> 32))
                    key[j] = ((unsigned long long)db << 32) | (unsigned)key[j];
                nb = nb > key[j] ? nb : key[j];
            }
            bkey = nb;
        }

        // block argmax over bucket keys
        unsigned long long wk = bkey;
#pragma unroll
        for (int o = 16; o; o >>= 1) {
            unsigned long long ok = __shfl_xor_sync(0xffffffffu, wk, o);
            if (ok > wk) wk = ok;
        }
        if (lane == 0) s_part[wid] = wk;
        __syncthreads();
        if (tid < 32) {
            unsigned long long k2 = s_part[tid];
#pragma unroll
            for (int o = 16; o; o >>= 1) {
                unsigned long long ok = __shfl_xor_sync(0xffffffffu, k2, o);
                if (ok > k2) k2 = ok;
            }
            if (tid == 0) s_win = k2;
        }
        __syncthreads();

        unsigned long long win = s_win;
        if (bkey == win) {          // owner thread broadcasts + emits outputs
            int jj = 0;
#pragma unroll
            for (int j = 0; j < 16; ++j)
                if (key[j] == win) jj = j;
            float ax = sx[jj * 1024 + tid];
            float ay = sy[jj * 1024 + tid];
            float az = sz[jj * 1024 + tid];
            s_q[0] = ax; s_q[1] = ay; s_q[2] = az;
            unsigned g = ~(unsigned)win;
            out[OFF_IND + b * NQ + it] = (float)g;
            float* oq = out + OFF_Q + ((size_t)b * NQ + it) * 3;
            oq[0] = ax; oq[1] = ay; oq[2] = az;
            float* gq = g_query + (b * NQ + it) * 3;
            gq[0] = ax; gq[1] = ay; gq[2] = az;
        }
        __syncthreads();
        qx = s_q[0]; qy = s_q[1]; qz = s_q[2];
    }
}

// ---------------------------------------------------------------------------
// KNN: warp-per-query exact top-(K+1) selection, ascending distance with
// lower-index tie-break (key = dist_bits<<32 | idx). Candidate-buffer filter
// with running 21st-best threshold; periodic warp merge.
// Distance matches reference pdist2: (sq_q + sq_p) - 2*dot (dot = FMA chain),
// clamped to >= 0.
// ---------------------------------------------------------------------------
__device__ __forceinline__ unsigned long long u64min(unsigned long long a,
                                                     unsigned long long b)
{ return a < b ? a : b; }

__device__ __forceinline__ void knn_flush(unsigned long long& cand,
                                          unsigned long long& curT,
                                          int& cnt,
                                          unsigned long long* buf,
                                          int lane)
{
    __syncwarp(0xffffffffu);
    unsigned long long r0 = cand;
    unsigned long long r1 = (lane      < cnt) ? buf[lane]      : ~0ULL;
    unsigned long long r2 = (lane + 32 < cnt) ? buf[lane + 32] : ~0ULL;
    unsigned long long r3 = (lane + 64 < cnt) ? buf[lane + 64] : ~0ULL;
    unsigned long long nc = ~0ULL;
#pragma unroll
    for (int r = 0; r < KK1; ++r) {
        unsigned long long m = u64min(u64min(r0, r1), u64min(r2, r3));
#pragma unroll
        for (int o = 16; o; o >>= 1) {
            unsigned long long om = __shfl_xor_sync(0xffffffffu, m, o);
            if (om < m) m = om;
        }
        if (lane == r) nc = m;
        if (r0 == m) r0 = ~0ULL;
        else if (r1 == m) r1 = ~0ULL;
        else if (r2 == m) r2 = ~0ULL;
        else if (r3 == m) r3 = ~0ULL;
    }
    cand = nc;
    curT = __shfl_sync(0xffffffffu, nc, KK1 - 1);
    cnt  = 0;
    __syncwarp(0xffffffffu);
}

__global__ __launch_bounds__(256)
void knn_kernel(const float* __restrict__ pts, int npts, int mode,
                float* __restrict__ outNbr, float* __restrict__ outD)
{
    __shared__ unsigned long long s_buf[8][96];
    const int warp = threadIdx.x >> 5;
    const int lane = threadIdx.x & 31;
    const int wg   = blockIdx.x * 8 + warp;      // 0..4095
    const int b    = wg >> 10;
    const int m    = wg & 1023;

    const float* Q = g_query + (b * NQ + m) * 3;
    float qx = Q[0], qy = Q[1], qz = Q[2];
    float sqq = __fadd_rn(__fadd_rn(__fmul_rn(qx, qx), __fmul_rn(qy, qy)),
                          __fmul_rn(qz, qz));

    const float* Pb = (mode == 0) ? (pts + (size_t)b * NPT * 3)
                                  : (g_query + b * NQ * 3);

    unsigned long long cand = ~0ULL, curT = ~0ULL;
    int cnt = 0;
    unsigned long long* buf = s_buf[warp];

    const int steps = npts >> 5;
    for (int j = 0; j < steps; ++j) {
        int i = (j << 5) + lane;
        const float* pp = Pb + i * 3;
        float px = __ldg(pp), py = __ldg(pp + 1), pz = __ldg(pp + 2);
        float sqp = __fadd_rn(__fadd_rn(__fmul_rn(px, px), __fmul_rn(py, py)),
                              __fmul_rn(pz, pz));
        float dot = __fmaf_rn(qz, pz, __fmaf_rn(qy, py, __fmul_rn(qx, px)));
        float d = fmaxf(__fsub_rn(__fadd_rn(sqq, sqp), __fmul_rn(2.0f, dot)),
                        0.0f);
        unsigned long long key =
            ((unsigned long long)__float_as_uint(d) << 32) | (unsigned)i;
        bool ins = key < curT;
        unsigned bal = __ballot_sync(0xffffffffu, ins);
        if (ins) buf[cnt + __popc(bal & ((1u << lane) - 1u))] = key;
        cnt += __popc(bal);
        if (cnt >= 64) knn_flush(cand, curT, cnt, buf, lane);
    }
    if (cnt > 0) knn_flush(cand, curT, cnt, buf, lane);

    if (lane >= 1 && lane < KK1) {
        unsigned idx = (unsigned)(cand & 0xFFFFFFFFu);
        size_t o = (size_t)wg * KK + (lane - 1);
        outNbr[o] = (float)idx;
        const float* ps = Pb + idx * 3;
        outD[o * 3 + 0] = qx - ps[0];
        outD[o * 3 + 1] = qy - ps[1];
        outD[o * 3 + 2] = qz - ps[2];
    }
}

extern "C" void kernel_launch(void* const* d_in, const int* in_sizes, int n_in,
                              void* d_out, int out_size)
{
    const float* points = (const float*)d_in[0];
    float* out = (float*)d_out;

    const int fps_smem = (3 * NPT + NCELL) * (int)sizeof(float);
    cudaFuncSetAttribute(fps_kernel,
                         cudaFuncAttributeMaxDynamicSharedMemorySize,
                         fps_smem);

    fps_kernel<<<NB, 1024, fps_smem>>>(points, out);

    // Gmid: neighbors of queries among all N points
    knn_kernel<<<(NB * NQ) / 8, 256>>>(points, NPT, 0,
                                       out + OFF_NM, out + OFF_DM);
    // Gout: neighbors of queries among queries
    knn_kernel<<<(NB * NQ) / 8, 256>>>(points, NQ, 1,
                                       out + OFF_NO, out + OFF_DO);
}

// round 5
// speedup vs baseline: 1.8205x; 1.2896x over previous
#include <cuda_runtime.h>

#define NB  4
#define NPT 16384
#define NQ  1024
#define KK  20
#define KK1 21
#define NCELL 4096

// output layout (all f32, concatenated in reference return order)
#define OFF_IND 0
#define OFF_Q   (NB*NQ)                   // 4096
#define OFF_NM  (OFF_Q  + NB*NQ*3)        // 16384
#define OFF_DM  (OFF_NM + NB*NQ*KK)       // 98304
#define OFF_NO  (OFF_DM + NB*NQ*KK*3)     // 344064
#define OFF_DO  (OFF_NO + NB*NQ*KK)       // 425984

__device__ float    g_query[NB*NQ*3];   // sampled query coords scratch
__device__ unsigned g_sidx[NB*NPT];     // sorted-pos -> original index

__device__ __forceinline__ unsigned morton4(unsigned cx, unsigned cy, unsigned cz)
{
    unsigned m = 0;
#pragma unroll
    for (int b = 0; b < 4; ++b)
        m |= (((cx >> b) & 1u) << (3 * b))
           | (((cy >> b) & 1u) << (3 * b + 1))
           | (((cz >> b) & 1u) << (3 * b + 2));
    return m;
}

__device__ __forceinline__ unsigned cellof(float x, float y, float z)
{
    unsigned cx = (unsigned)fminf(fmaxf((x + 4.0f) * 2.0f, 0.0f), 15.0f);
    unsigned cy = (unsigned)fminf(fmaxf((y + 4.0f) * 2.0f, 0.0f), 15.0f);
    unsigned cz = (unsigned)fminf(fmaxf((z + 4.0f) * 2.0f, 0.0f), 15.0f);
    return morton4(cx, cy, cz);
}

// ---------------------------------------------------------------------------
// Bucketed FPS, one CTA per batch.
// - Morton counting sort into transposed SoA smem (thread t's bucket point j
//   at [j*1024+t], conflict-free).
// - Each thread owns one 16-point bucket: packed u64 keys
//   (min_d_bits<<32 | ~orig_idx) in registers + bbox. Bucket updates only
//   when its bbox lower bound can beat its max min_d (skips provably exact).
// - Argmax per iteration: two-stage reduce with ONE barrier. Stage 1:
//   __reduce_max_sync on dist bits then on tie-break (~idx). Lane 0 stores
//   per-warp (d,i) into double-buffered smem. After the barrier every warp
//   redundantly reduces the 32 partials (no 2nd barrier).
// - rank[origidx]->sorted slot table (u16, overlaid on hist smem) lets all
//   threads fetch the winner's coords directly: no owner broadcast.
// - Distance form matches the reference scan exactly: plain (non-contracted)
//   left-to-right sum of squares.
// ---------------------------------------------------------------------------
__global__ __launch_bounds__(1024, 1)
void fps_kernel(const float* __restrict__ pts, float* __restrict__ out)
{
    extern __shared__ float sm[];
    float*          sx   = sm;
    float*          sy   = sm + NPT;
    float*          sz   = sm + 2 * NPT;
    unsigned*       hist = (unsigned*)(sm + 3 * NPT);        // 16KB (sort only)
    unsigned short* rank = (unsigned short*)(sm + 3 * NPT);  // 32KB (after sort)

    __shared__ unsigned s_pd[2][32];
    __shared__ unsigned s_pi[2][32];
    __shared__ unsigned s_wsum[32];

    const int b    = blockIdx.x;
    const int tid  = threadIdx.x;
    const int lane = tid & 31, wid = tid >> 5;
    const float* P = pts + (size_t)b * NPT * 3;
    unsigned* sidx = g_sidx + b * NPT;

    // ---- counting sort by Morton cell ----
#pragma unroll
    for (int k = 0; k < 4; ++k) hist[tid + k * 1024] = 0;
    __syncthreads();

#pragma unroll
    for (int k = 0; k < 16; ++k) {
        int i = tid + k * 1024;
        float x = P[i * 3], y = P[i * 3 + 1], z = P[i * 3 + 2];
        atomicAdd(&hist[cellof(x, y, z)], 1u);
    }
    __syncthreads();

    // exclusive scan of hist[4096] in place
    unsigned v0 = hist[4 * tid], v1 = hist[4 * tid + 1];
    unsigned v2 = hist[4 * tid + 2], v3 = hist[4 * tid + 3];
    unsigned s = v0 + v1 + v2 + v3;
    unsigned inc = s;
#pragma unroll
    for (int o = 1; o < 32; o <<= 1) {
        unsigned n = __shfl_up_sync(0xffffffffu, inc, o);
        if (lane >= o) inc += n;
    }
    if (lane == 31) s_wsum[wid] = inc;
    __syncthreads();
    if (tid < 32) {
        unsigned w = s_wsum[tid], wi = w;
#pragma unroll
        for (int o = 1; o < 32; o <<= 1) {
            unsigned n = __shfl_up_sync(0xffffffffu, wi, o);
            if (tid >= o) wi += n;
        }
        s_wsum[tid] = wi - w;   // exclusive warp base
    }
    __syncthreads();
    unsigned base = s_wsum[wid] + inc - s;
    hist[4 * tid]     = base;
    hist[4 * tid + 1] = base + v0;
    hist[4 * tid + 2] = base + v0 + v1;
    hist[4 * tid + 3] = base + v0 + v1 + v2;
    __syncthreads();

    // scatter: sorted pos p -> smem slot (p%16)*1024 + p/16
#pragma unroll
    for (int k = 0; k < 16; ++k) {
        int i = tid + k * 1024;
        float x = P[i * 3], y = P[i * 3 + 1], z = P[i * 3 + 2];
        unsigned pos = atomicAdd(&hist[cellof(x, y, z)], 1u);
        int slot = (int)(pos & 15u) * 1024 + (int)(pos >> 4);
        sx[slot] = x; sy[slot] = y; sz[slot] = z;
        sidx[pos] = (unsigned)i;
    }
    __syncthreads();   // scatter (and all hist use) complete

    // ---- rank table (overwrites hist region) + per-bucket state ----
#pragma unroll
    for (int k = 0; k < 16; ++k) {
        int pos = tid + k * 1024;
        rank[sidx[pos]] = (unsigned short)pos;
    }

    unsigned long long key[16];
    float lox = 1e30f, loy = 1e30f, loz = 1e30f;
    float hix = -1e30f, hiy = -1e30f, hiz = -1e30f;
    const unsigned long long HI10 =
        ((unsigned long long)__float_as_uint(1e10f)) << 32;
    unsigned long long bkey = 0;
#pragma unroll
    for (int j = 0; j < 16; ++j) {
        float x = sx[j * 1024 + tid];
        float y = sy[j * 1024 + tid];
        float z = sz[j * 1024 + tid];
        lox = fminf(lox, x); hix = fmaxf(hix, x);
        loy = fminf(loy, y); hiy = fmaxf(hiy, y);
        loz = fminf(loz, z); hiz = fmaxf(hiz, z);
        key[j] = HI10 | (unsigned)(~sidx[16 * tid + j]);
        bkey = bkey > key[j] ? bkey : key[j];
    }
    __syncthreads();   // rank visible

    // first sample = original index 0
    float qx, qy, qz;
    {
        int slot0 = rank[0];
        int a0 = (slot0 & 15) * 1024 + (slot0 >> 4);
        qx = sx[a0]; qy = sy[a0]; qz = sz[a0];
        if (tid == 0) {
            out[OFF_IND + b * NQ] = 0.0f;
            float* oq = out + OFF_Q + (size_t)b * NQ * 3;
            oq[0] = qx; oq[1] = qy; oq[2] = qz;
            float* gq = g_query + b * NQ * 3;
            gq[0] = qx; gq[1] = qy; gq[2] = qz;
        }
    }

    // ---- main FPS loop: one barrier per iteration ----
    for (int it = 1; it < NQ; ++it) {
        float dx = fmaxf(fmaxf(lox - qx, qx - hix), 0.0f);
        float dy = fmaxf(fmaxf(loy - qy, qy - hiy), 0.0f);
        float dz = fmaxf(fmaxf(loz - qz, qz - hiz), 0.0f);
        float lb2 = dx * dx + dy * dy + dz * dz;
        unsigned bd = (unsigned)(bkey >> 32);
        if (lb2 * 0.999f < __uint_as_float(bd)) {
            unsigned long long nb = 0;
#pragma unroll
            for (int j = 0; j < 16; ++j) {
                float t0 = sx[j * 1024 + tid] - qx;
                float t1 = sy[j * 1024 + tid] - qy;
                float t2 = sz[j * 1024 + tid] - qz;
                // plain (non-contracted) sum of squares, left-to-right
                float d = __fadd_rn(__fadd_rn(__fmul_rn(t0, t0),
                                              __fmul_rn(t1, t1)),
                                    __fmul_rn(t2, t2));
                unsigned db = __float_as_uint(d);
                if (db < (unsigned)(key[j] >> 32))
                    key[j] = ((unsigned long long)db << 32) | (unsigned)key[j];
                nb = nb > key[j] ? nb : key[j];
            }
            bkey = nb;
            bd = (unsigned)(bkey >> 32);
        }
        unsigned bi = (unsigned)bkey;

        // stage 1: warp argmax (dist, then ~idx) via redux
        unsigned dmax = __reduce_max_sync(0xffffffffu, bd);
        unsigned imax = __reduce_max_sync(0xffffffffu, (bd == dmax) ? bi : 0u);
        const int p = it & 1;
        if (lane == 0) { s_pd[p][wid] = dmax; s_pi[p][wid] = imax; }
        __syncthreads();

        // stage 2: every warp reduces the 32 partials (no 2nd barrier)
        unsigned d2 = s_pd[p][lane];
        unsigned i2 = s_pi[p][lane];
        unsigned dW = __reduce_max_sync(0xffffffffu, d2);
        unsigned iW = __reduce_max_sync(0xffffffffu, (d2 == dW) ? i2 : 0u);
        unsigned g  = ~iW;

        int slot = rank[g];
        int addr = (slot & 15) * 1024 + (slot >> 4);
        qx = sx[addr]; qy = sy[addr]; qz = sz[addr];

        if (tid == 0) {
            out[OFF_IND + b * NQ + it] = (float)g;
            float* oq = out + OFF_Q + ((size_t)b * NQ + it) * 3;
            oq[0] = qx; oq[1] = qy; oq[2] = qz;
            float* gq = g_query + (b * NQ + it) * 3;
            gq[0] = qx; gq[1] = qy; gq[2] = qz;
        }
    }
}

// ---------------------------------------------------------------------------
// KNN: warp-per-query exact top-(K+1), ascending (dist, idx) keys.
// Candidate buffer + running 21st-best threshold; flush selection uses redux
// min pairs. Distance matches reference pdist2: (sq_q+sq_p) - 2*dot (FMA dot),
// clamped >= 0.
// ---------------------------------------------------------------------------
__device__ __forceinline__ unsigned long long u64min(unsigned long long a,
                                                     unsigned long long b)
{ return a < b ? a : b; }

__device__ __forceinline__ void knn_flush(unsigned long long& cand,
                                          unsigned long long& curT,
                                          int& cnt,
                                          unsigned long long* buf,
                                          int lane)
{
    __syncwarp(0xffffffffu);
    unsigned long long r0 = cand;
    unsigned long long r1 = (lane      < cnt) ? buf[lane]      : ~0ULL;
    unsigned long long r2 = (lane + 32 < cnt) ? buf[lane + 32] : ~0ULL;
    unsigned long long r3 = (lane + 64 < cnt) ? buf[lane + 64] : ~0ULL;
    unsigned long long nc = ~0ULL;
#pragma unroll
    for (int r = 0; r < KK1; ++r) {
        unsigned long long m = u64min(u64min(r0, r1), u64min(r2, r3));
        unsigned md = (unsigned)(m >> 32), mi = (unsigned)m;
        unsigned dmin = __reduce_min_sync(0xffffffffu, md);
        unsigned imin = __reduce_min_sync(0xffffffffu,
                                          (md == dmin) ? mi : 0xFFFFFFFFu);
        unsigned long long w = ((unsigned long long)dmin << 32) | imin;
        if (lane == r) nc = w;
        if (r0 == w) r0 = ~0ULL;
        else if (r1 == w) r1 = ~0ULL;
        else if (r2 == w) r2 = ~0ULL;
        else if (r3 == w) r3 = ~0ULL;
    }
    cand = nc;
    curT = __shfl_sync(0xffffffffu, nc, KK1 - 1);
    cnt  = 0;
    __syncwarp(0xffffffffu);
}

__global__ __launch_bounds__(256)
void knn_kernel(const float* __restrict__ pts, int npts, int mode,
                float* __restrict__ outNbr, float* __restrict__ outD)
{
    __shared__ unsigned long long s_buf[8][96];
    const int warp = threadIdx.x >> 5;
    const int lane = threadIdx.x & 31;
    const int wg   = blockIdx.x * 8 + warp;      // 0..4095
    const int b    = wg >> 10;
    const int m    = wg & 1023;

    const float* Q = g_query + (b * NQ + m) * 3;
    float qx = Q[0], qy = Q[1], qz = Q[2];
    float sqq = __fadd_rn(__fadd_rn(__fmul_rn(qx, qx), __fmul_rn(qy, qy)),
                          __fmul_rn(qz, qz));

    const float* Pb = (mode == 0) ? (pts + (size_t)b * NPT * 3)
                                  : (g_query + b * NQ * 3);

    unsigned long long cand = ~0ULL, curT = ~0ULL;
    int cnt = 0;
    unsigned long long* buf = s_buf[warp];
    const unsigned ltmask = (1u << lane) - 1u;

    const int steps = npts >> 5;   // multiple of 2 for both modes
    for (int j = 0; j < steps; j += 2) {
        int i0 = (j << 5) + lane;
        int i1 = i0 + 32;
        const float* p0 = Pb + i0 * 3;
        const float* p1 = Pb + i1 * 3;
        float ax = __ldg(p0), ay = __ldg(p0 + 1), az = __ldg(p0 + 2);
        float bx = __ldg(p1), by = __ldg(p1 + 1), bz = __ldg(p1 + 2);

        float sa = __fadd_rn(__fadd_rn(__fmul_rn(ax, ax), __fmul_rn(ay, ay)),
                             __fmul_rn(az, az));
        float da = __fmaf_rn(qz, az, __fmaf_rn(qy, ay, __fmul_rn(qx, ax)));
        float d0 = fmaxf(__fsub_rn(__fadd_rn(sqq, sa), __fmul_rn(2.0f, da)),
                         0.0f);
        float sb = __fadd_rn(__fadd_rn(__fmul_rn(bx, bx), __fmul_rn(by, by)),
                             __fmul_rn(bz, bz));
        float db = __fmaf_rn(qz, bz, __fmaf_rn(qy, by, __fmul_rn(qx, bx)));
        float d1 = fmaxf(__fsub_rn(__fadd_rn(sqq, sb), __fmul_rn(2.0f, db)),
                         0.0f);

        unsigned long long k0 =
            ((unsigned long long)__float_as_uint(d0) << 32) | (unsigned)i0;
        unsigned long long k1 =
            ((unsigned long long)__float_as_uint(d1) << 32) | (unsigned)i1;

        bool in0 = k0 < curT;
        unsigned b0 = __ballot_sync(0xffffffffu, in0);
        if (in0) buf[cnt + __popc(b0 & ltmask)] = k0;
        cnt += __popc(b0);

        bool in1 = k1 < curT;
        unsigned b1 = __ballot_sync(0xffffffffu, in1);
        if (in1) buf[cnt + __popc(b1 & ltmask)] = k1;
        cnt += __popc(b1);

        if (cnt >= 32) knn_flush(cand, curT, cnt, buf, lane);
    }
    if (cnt > 0) knn_flush(cand, curT, cnt, buf, lane);

    if (lane >= 1 && lane < KK1) {
        unsigned idx = (unsigned)(cand & 0xFFFFFFFFu);
        size_t o = (size_t)wg * KK + (lane - 1);
        outNbr[o] = (float)idx;
        const float* ps = Pb + idx * 3;
        outD[o * 3 + 0] = qx - ps[0];
        outD[o * 3 + 1] = qy - ps[1];
        outD[o * 3 + 2] = qz - ps[2];
    }
}

extern "C" void kernel_launch(void* const* d_in, const int* in_sizes, int n_in,
                              void* d_out, int out_size)
{
    const float* points = (const float*)d_in[0];
    float* out = (float*)d_out;

    const int fps_smem = 3 * NPT * (int)sizeof(float)
                       + NPT * (int)sizeof(unsigned short);   // 229376 B
    cudaFuncSetAttribute(fps_kernel,
                         cudaFuncAttributeMaxDynamicSharedMemorySize,
                         fps_smem);

    fps_kernel<<<NB, 1024, fps_smem>>>(points, out);

    // Gmid: neighbors of queries among all N points
    knn_kernel<<<(NB * NQ) / 8, 256>>>(points, NPT, 0,
                                       out + OFF_NM, out + OFF_DM);
    // Gout: neighbors of queries among queries
    knn_kernel<<<(NB * NQ) / 8, 256>>>(points, NQ, 1,
                                       out + OFF_NO, out + OFF_DO);
}